// round 16
// baseline (speedup 1.0000x reference)
#include <cuda_runtime.h>
#include <cstdint>

// Problem constants (fixed by the dataset)
#define NTAB     8
#define BUCKETS  524288          // 2^19
#define BMASK    (BUCKETS - 1)
#define T_LEN    4096
#define HIST     128             // deepest lag
#define POS      64              // positions per block
#define THREADS  256
#define EXT      (POS + 120)     // 184: h8 needed at positions [t0-120, t0+POS)
#define U32B_PB  (POS * NTAB * 8)            // 4096 32-byte units per block
#define BATCH    4                           // 4 x 32B in flight per phase
#define PHASES   (U32B_PB / (THREADS * BATCH)) // 4 phases

// Hash primes (low-32-bit arithmetic is exact for the %2^19 result)
#define P0 2654435761u
#define P1 2246822519u
#define P2 3266489917u
#define P3 2028178513u
#define P4 1220703125u
#define P5 1610612741u
#define P6 805306457u
#define P7 402653189u

__global__ void __launch_bounds__(THREADS, 5)
hash_tables_kernel(const void*   __restrict__ tokens_raw,
                   const float4* __restrict__ tables,   // [8, 524288, 64] fp32 as float4
                   float4*       __restrict__ out)      // [B, T, 512] fp32 as float4
{
    __shared__ int      tok_s[HIST + POS];   // 192 staged tokens (zero-padded)
    __shared__ unsigned A[EXT], Bf[EXT];     // ping-pong window-hash arrays
    __shared__ int      idx_s[POS * NTAB];   // bucket ids, [pos][window]
    __shared__ int      is32_s;

    const int*       tok32 = (const int*)tokens_raw;
    const long long* tok64 = (const long long*)tokens_raw;
    const int tid = threadIdx.x;

    // ---- Inline dtype probe: int64 tokens (<2^31) have all-zero odd words ----
    if (tid < 32) {
        unsigned any = __ballot_sync(0xFFFFFFFFu, tok32[2 * tid + 1] != 0);
        if (tid == 0) is32_s = (any != 0u);
    }

    const int groups_per_row = T_LEN / POS;       // 64
    const int row = blockIdx.x / groups_per_row;
    const int t0  = (blockIdx.x % groups_per_row) * POS;

    __syncthreads();
    const int is32 = is32_s;

    // ---- Phase 1: stage tokens t0-128 .. t0+POS-1 (zero-padded) ----
    for (int i = tid; i < HIST + POS; i += THREADS) {
        const int t = t0 - HIST + i;
        int v = 0;
        if (t >= 0) {
            const size_t k = (size_t)row * T_LEN + t;
            v = is32 ? tok32[k] : (int)tok64[k];
        }
        tok_s[i] = v;
    }
    __syncthreads();

    // ---- Phase 2a: h1,h2,h4,h8 chains. Position p = t0-120+i; lag-k token
    // is tok_s[i+7-k]. Snapshots for gather positions (i >= 120). ----
    if (tid < EXT) {
        const int i = tid;
        const bool snap = (i >= 120);
        const int  tp   = i - 120;
        unsigned h = (unsigned)tok_s[i + 7] * P0;                    // window 1
        if (snap) idx_s[tp * NTAB + 0] = (int)(h & BMASK);
        h ^= (unsigned)tok_s[i + 6] * P1;                            // window 2
        if (snap) idx_s[tp * NTAB + 1] = (int)(h & BMASK);
        h ^= (unsigned)tok_s[i + 5] * P2;
        h ^= (unsigned)tok_s[i + 4] * P3;                            // window 4
        if (snap) idx_s[tp * NTAB + 2] = (int)(h & BMASK);
        h ^= (unsigned)tok_s[i + 3] * P4;
        h ^= (unsigned)tok_s[i + 2] * P5;
        h ^= (unsigned)tok_s[i + 1] * P6;
        h ^= (unsigned)tok_s[i + 0] * P7;                            // window 8
        A[i] = h;
        if (snap) idx_s[tp * NTAB + 3] = (int)(h & BMASK);
    }
    __syncthreads();

    // ---- Phase 2b: log-doubling. h_{2w}(p) = h_w(p) ^ h_w(p-w). ----
    if (tid < EXT && tid >= 8) {                 // window 16
        unsigned h = A[tid] ^ A[tid - 8];
        Bf[tid] = h;
        if (tid >= 120) idx_s[(tid - 120) * NTAB + 4] = (int)(h & BMASK);
    }
    __syncthreads();
    if (tid < EXT && tid >= 24) {                // window 32
        unsigned h = Bf[tid] ^ Bf[tid - 16];
        A[tid] = h;
        if (tid >= 120) idx_s[(tid - 120) * NTAB + 5] = (int)(h & BMASK);
    }
    __syncthreads();
    if (tid < EXT && tid >= 56) {                // window 64
        unsigned h = A[tid] ^ A[tid - 32];
        Bf[tid] = h;
        if (tid >= 120) idx_s[(tid - 120) * NTAB + 6] = (int)(h & BMASK);
    }
    __syncthreads();
    if (tid >= 120 && tid < EXT) {               // window 128
        unsigned h = Bf[tid] ^ Bf[tid - 64];
        idx_s[(tid - 120) * NTAB + 7] = (int)(h & BMASK);
    }
    __syncthreads();

    // ---- Phase 3: 256-bit gathers (4x32B in flight per phase, 4 phases)
    // + 256-bit cache-streaming stores. 32B unit u: table row rw = u>>3
    // (= pos*8 + tbl), 32B chunk c8 = u&7.
    const size_t out32 = (((size_t)row * T_LEN + t0) << 7) >> 1;   // 32B units

    #pragma unroll
    for (int ph = 0; ph < PHASES; ++ph) {
        const int base = ph * THREADS * BATCH;

        const char* src[BATCH];
        #pragma unroll
        for (int it = 0; it < BATCH; ++it) {
            const int u  = base + it * THREADS + tid;
            const int rw = u >> 3;                   // row = pos*8 + tbl
            const int c8 = u & 7;                    // 32B chunk in row
            const int tbl = rw & 7;
            const int bucket = idx_s[rw];
            src[it] = (const char*)tables
                + ((((size_t)tbl * BUCKETS + (size_t)bucket) << 8) | ((size_t)c8 << 5));
        }

        unsigned long long d0[BATCH], d1[BATCH], d2[BATCH], d3[BATCH];
        #pragma unroll
        for (int it = 0; it < BATCH; ++it) {
            asm volatile("ld.global.nc.L2::evict_last.v4.b64 {%0,%1,%2,%3}, [%4];"
                         : "=l"(d0[it]), "=l"(d1[it]), "=l"(d2[it]), "=l"(d3[it])
                         : "l"(src[it]));
        }
        #pragma unroll
        for (int it = 0; it < BATCH; ++it) {
            char* dst = (char*)out
                + ((out32 + (size_t)(base + it * THREADS + tid)) << 5);
            asm volatile("st.global.cs.v4.b64 [%0], {%1,%2,%3,%4};"
                         :: "l"(dst), "l"(d0[it]), "l"(d1[it]),
                            "l"(d2[it]), "l"(d3[it])
                         : "memory");
        }
    }
}

extern "C" void kernel_launch(void* const* d_in, const int* in_sizes, int n_in,
                              void* d_out, int out_size)
{
    const void*   tokens = d_in[0];               // int64 OR int32 (B, T) — probed
    const float4* tables = (const float4*)d_in[1];// fp32 (8, 524288, 64)
    float4*       out    = (float4*)d_out;        // fp32 (B, T, 512)

    const int rows = in_sizes[0] / T_LEN;         // B = 8
    const int grid = rows * (T_LEN / POS);        // 512 blocks
    hash_tables_kernel<<<grid, THREADS>>>(tokens, tables, out);
}

// round 17
// speedup vs baseline: 1.2000x; 1.2000x over previous
#include <cuda_runtime.h>
#include <cstdint>

// Problem constants (fixed by the dataset)
#define NTAB     8
#define BUCKETS  524288          // 2^19
#define BMASK    (BUCKETS - 1)
#define T_LEN    4096
#define HIST     128             // deepest lag
#define POS      64              // positions per block
#define THREADS  256
#define EXT      (POS + 120)     // 184: h8 needed at positions [t0-120, t0+POS)
#define U32B_PB  (POS * NTAB * 8)            // 4096 32-byte units per block
#define BATCH    4                           // 4 x 32B in flight per phase
#define PHASES   (U32B_PB / (THREADS * BATCH)) // 4 phases

// Hash primes (low-32-bit arithmetic is exact for the %2^19 result)
#define P0 2654435761u
#define P1 2246822519u
#define P2 3266489917u
#define P3 2028178513u
#define P4 1220703125u
#define P5 1610612741u
#define P6 805306457u
#define P7 402653189u

__global__ void __launch_bounds__(THREADS, 5)
hash_tables_kernel(const void*   __restrict__ tokens_raw,
                   const float4* __restrict__ tables,   // [8, 524288, 64] fp32 as float4
                   float4*       __restrict__ out)      // [B, T, 512] fp32 as float4
{
    __shared__ int      tok_s[HIST + POS];   // 192 staged tokens (zero-padded)
    __shared__ unsigned A[EXT], Bf[EXT];     // ping-pong window-hash arrays
    __shared__ int      idx_s[POS * NTAB];   // bucket ids, [pos][window]
    __shared__ int      is32_s;

    const int*       tok32 = (const int*)tokens_raw;
    const long long* tok64 = (const long long*)tokens_raw;
    const int tid = threadIdx.x;

    // ---- Inline dtype probe: int64 tokens (<2^31) have all-zero odd words ----
    if (tid < 32) {
        unsigned any = __ballot_sync(0xFFFFFFFFu, tok32[2 * tid + 1] != 0);
        if (tid == 0) is32_s = (any != 0u);
    }

    const int groups_per_row = T_LEN / POS;       // 64
    const int row = blockIdx.x / groups_per_row;
    const int t0  = (blockIdx.x % groups_per_row) * POS;

    __syncthreads();
    const int is32 = is32_s;

    // ---- Phase 1: stage tokens t0-128 .. t0+POS-1 (zero-padded) ----
    for (int i = tid; i < HIST + POS; i += THREADS) {
        const int t = t0 - HIST + i;
        int v = 0;
        if (t >= 0) {
            const size_t k = (size_t)row * T_LEN + t;
            v = is32 ? tok32[k] : (int)tok64[k];
        }
        tok_s[i] = v;
    }
    __syncthreads();

    // ---- Phase 2a: h1,h2,h4,h8 chains. Position p = t0-120+i; lag-k token
    // is tok_s[i+7-k]. Snapshots for gather positions (i >= 120). ----
    if (tid < EXT) {
        const int i = tid;
        const bool snap = (i >= 120);
        const int  tp   = i - 120;
        unsigned h = (unsigned)tok_s[i + 7] * P0;                    // window 1
        if (snap) idx_s[tp * NTAB + 0] = (int)(h & BMASK);
        h ^= (unsigned)tok_s[i + 6] * P1;                            // window 2
        if (snap) idx_s[tp * NTAB + 1] = (int)(h & BMASK);
        h ^= (unsigned)tok_s[i + 5] * P2;
        h ^= (unsigned)tok_s[i + 4] * P3;                            // window 4
        if (snap) idx_s[tp * NTAB + 2] = (int)(h & BMASK);
        h ^= (unsigned)tok_s[i + 3] * P4;
        h ^= (unsigned)tok_s[i + 2] * P5;
        h ^= (unsigned)tok_s[i + 1] * P6;
        h ^= (unsigned)tok_s[i + 0] * P7;                            // window 8
        A[i] = h;
        if (snap) idx_s[tp * NTAB + 3] = (int)(h & BMASK);
    }
    __syncthreads();

    // ---- Phase 2b: log-doubling. h_{2w}(p) = h_w(p) ^ h_w(p-w). ----
    if (tid < EXT && tid >= 8) {                 // window 16
        unsigned h = A[tid] ^ A[tid - 8];
        Bf[tid] = h;
        if (tid >= 120) idx_s[(tid - 120) * NTAB + 4] = (int)(h & BMASK);
    }
    __syncthreads();
    if (tid < EXT && tid >= 24) {                // window 32
        unsigned h = Bf[tid] ^ Bf[tid - 16];
        A[tid] = h;
        if (tid >= 120) idx_s[(tid - 120) * NTAB + 5] = (int)(h & BMASK);
    }
    __syncthreads();
    if (tid < EXT && tid >= 56) {                // window 64
        unsigned h = A[tid] ^ A[tid - 32];
        Bf[tid] = h;
        if (tid >= 120) idx_s[(tid - 120) * NTAB + 6] = (int)(h & BMASK);
    }
    __syncthreads();
    if (tid >= 120 && tid < EXT) {               // window 128
        unsigned h = Bf[tid] ^ Bf[tid - 64];
        idx_s[(tid - 120) * NTAB + 7] = (int)(h & BMASK);
    }
    __syncthreads();

    // ---- Phase 3: 256-bit gathers (4x32B in flight per phase, 4 phases)
    // + 256-bit streaming stores. 32B unit u: table row rw = u>>3
    // (= pos*8 + tbl), 32B chunk c8 = u&7. Block covers all 4096 units
    // of its 64-position group.
    const size_t out32 = (((size_t)row * T_LEN + t0) << 7) >> 1;   // 32B units

    #pragma unroll
    for (int ph = 0; ph < PHASES; ++ph) {
        const int base = ph * THREADS * BATCH;

        const char* src[BATCH];
        #pragma unroll
        for (int it = 0; it < BATCH; ++it) {
            const int u  = base + it * THREADS + tid;
            const int rw = u >> 3;                   // row = pos*8 + tbl
            const int c8 = u & 7;                    // 32B chunk in row
            const int tbl = rw & 7;
            const int bucket = idx_s[rw];
            src[it] = (const char*)tables
                + ((((size_t)tbl * BUCKETS + (size_t)bucket) << 8) | ((size_t)c8 << 5));
        }

        unsigned long long d0[BATCH], d1[BATCH], d2[BATCH], d3[BATCH];
        #pragma unroll
        for (int it = 0; it < BATCH; ++it) {
            asm volatile("ld.global.nc.L2::evict_last.v4.b64 {%0,%1,%2,%3}, [%4];"
                         : "=l"(d0[it]), "=l"(d1[it]), "=l"(d2[it]), "=l"(d3[it])
                         : "l"(src[it]));
        }
        #pragma unroll
        for (int it = 0; it < BATCH; ++it) {
            char* dst = (char*)out
                + ((out32 + (size_t)(base + it * THREADS + tid)) << 5);
            asm volatile("st.global.L2::evict_first.v4.b64 [%0], {%1,%2,%3,%4};"
                         :: "l"(dst), "l"(d0[it]), "l"(d1[it]), "l"(d2[it]), "l"(d3[it])
                         : "memory");
        }
    }
}

extern "C" void kernel_launch(void* const* d_in, const int* in_sizes, int n_in,
                              void* d_out, int out_size)
{
    const void*   tokens = d_in[0];               // int64 OR int32 (B, T) — probed
    const float4* tables = (const float4*)d_in[1];// fp32 (8, 524288, 64)
    float4*       out    = (float4*)d_out;        // fp32 (B, T, 512)

    const int rows = in_sizes[0] / T_LEN;         // B = 8
    const int grid = rows * (T_LEN / POS);        // 512 blocks
    hash_tables_kernel<<<grid, THREADS>>>(tokens, tables, out);
}